// round 14
// baseline (speedup 1.0000x reference)
#include <cuda_runtime.h>
#include <cuda_fp16.h>
#include <cuda_fp8.h>
#include <stdint.h>
#include <math.h>

// Problem constants
#define Bsz 4
#define Cch 128
#define Nn 4096
#define NH 4
#define Dd 32
// 1/sqrt(32) * log2(e): fold softmax scale AND exp2 conversion into Q
#define QSCALE (0.17677669529663687f * 1.4426950408889634f)

// Scratch (__device__ globals; allocation-free rule)
__device__ __half g_Wh[4*Cch*Cch];            // wq,wk,wv,wo as f16 (o, c)
__device__ __half g_Xh[Bsz*Nn*Cch];           // x transposed to (b, n, c) f16
__device__ unsigned char g_Qf8[Bsz*NH*Nn*Dd]; // (bh, n, d) e4m3, scaled QSCALE*16
__device__ unsigned char g_Kf8[Bsz*NH*Nn*Dd]; // (bh, n, d) e4m3
__device__ __half g_Vt[Bsz*NH*Dd*Nn];         // (bh, d, n) f16
__device__ __half g_attnh[Bsz*Nn*Cch];        // (b, n, c) token-major

// ---------------------------------------------------------------------------
__device__ __forceinline__ void mmaf16(float&c0,float&c1,float&c2,float&c3,
    uint32_t a0,uint32_t a1,uint32_t a2,uint32_t a3,uint32_t b0,uint32_t b1)
{
    asm volatile("mma.sync.aligned.m16n8k16.row.col.f32.f16.f16.f32 "
        "{%0,%1,%2,%3},{%4,%5,%6,%7},{%8,%9},{%0,%1,%2,%3};"
        : "+f"(c0),"+f"(c1),"+f"(c2),"+f"(c3)
        : "r"(a0),"r"(a1),"r"(a2),"r"(a3),"r"(b0),"r"(b1));
}
// FP8 e4m3 mma: m16n8k32, f32 accum (sm_89+ baseline, not 'a'-gated)
__device__ __forceinline__ void mmaf8(float&c0,float&c1,float&c2,float&c3,
    uint32_t a0,uint32_t a1,uint32_t a2,uint32_t a3,uint32_t b0,uint32_t b1)
{
    asm volatile("mma.sync.aligned.m16n8k32.row.col.f32.e4m3.e4m3.f32 "
        "{%0,%1,%2,%3},{%4,%5,%6,%7},{%8,%9},{%0,%1,%2,%3};"
        : "+f"(c0),"+f"(c1),"+f"(c2),"+f"(c3)
        : "r"(a0),"r"(a1),"r"(a2),"r"(a3),"r"(b0),"r"(b1));
}
__device__ __forceinline__ void ldmx4(uint32_t* r, const void* p) {
    uint32_t a = (uint32_t)__cvta_generic_to_shared(p);
    asm volatile("ldmatrix.sync.aligned.m8n8.x4.shared.b16 {%0,%1,%2,%3}, [%4];"
        : "=r"(r[0]),"=r"(r[1]),"=r"(r[2]),"=r"(r[3]) : "r"(a));
}
__device__ __forceinline__ void ldmx2(uint32_t* r, const void* p) {
    uint32_t a = (uint32_t)__cvta_generic_to_shared(p);
    asm volatile("ldmatrix.sync.aligned.m8n8.x2.shared.b16 {%0,%1}, [%2];"
        : "=r"(r[0]),"=r"(r[1]) : "r"(a));
}
__device__ __forceinline__ void cp16(void* smem, const void* g) {
    uint32_t a = (uint32_t)__cvta_generic_to_shared(smem);
    asm volatile("cp.async.ca.shared.global [%0], [%1], 16;" :: "r"(a), "l"(g));
}
__device__ __forceinline__ void cp_commit() {
    asm volatile("cp.async.commit_group;");
}
__device__ __forceinline__ void cp_wait0() {
    asm volatile("cp.async.wait_group 0;" ::: "memory");
}
__device__ __forceinline__ uint32_t h2u(__half2 h) { return *(uint32_t*)&h; }
__device__ __forceinline__ unsigned char f2e4m3(float v) {
    return (unsigned char)__nv_cvt_float_to_fp8(v, __NV_SATFINITE, __NV_E4M3);
}

// ===========================================================================
// Kernel 0: prep — W -> f16, x -> f16 transposed (b, n, c).  Fat blocks.
// ===========================================================================
__global__ __launch_bounds__(256) void prep_kernel(
    const float* __restrict__ x,
    const float* __restrict__ wq, const float* __restrict__ wk,
    const float* __restrict__ wv, const float* __restrict__ wo)
{
    const int bid = blockIdx.x;
    const int tid = threadIdx.x;
    if (bid < 512) {
        __shared__ float tile[64][65];
        const int b  = bid >> 7;
        const int c0 = ((bid >> 6) & 1) * 64;
        const int n0 = (bid & 63) * 64;
        #pragma unroll
        for (int i = 0; i < 16; ++i) {
            int idx = tid + i*256;
            int c = idx >> 6, n = idx & 63;
            tile[c][n] = x[((size_t)b*Cch + c0 + c)*Nn + n0 + n];
        }
        __syncthreads();
        #pragma unroll
        for (int i = 0; i < 8; ++i) {
            int idx = tid + i*256;
            int n = idx >> 5, cp = idx & 31;
            int c = cp*2;
            *(half2*)&g_Xh[((size_t)b*Nn + n0 + n)*Cch + c0 + c] =
                __floats2half2_rn(tile[c][n], tile[c+1][n]);
        }
    } else {
        const int wb = bid - 512;
        #pragma unroll
        for (int i = 0; i < 8; ++i) {
            int idx = wb*2048 + i*256 + tid;
            int m = idx >> 14, rr = idx & 16383;
            const float* W = (m==0) ? wq : (m==1) ? wk : (m==2) ? wv : wo;
            g_Wh[idx] = __float2half(W[rr]);
        }
    }
}

// ===========================================================================
// Kernel 1: fused QKV projection, cp.async double-buffered f16 pipeline.
// Q/K now stored as e4m3 bytes (n, d); V^T stays f16.
// ===========================================================================
#define XSTR 136
#define WSTR 40
__global__ __launch_bounds__(256, 2) void qkv_kernel(
    const float* __restrict__ bq, const float* __restrict__ bk,
    const float* __restrict__ bv)
{
    __shared__ __align__(16) __half Xs[64*XSTR];
    __shared__ __align__(16) __half Ws[2][128*WSTR];

    const int tile = blockIdx.x;
    const int b  = tile >> 6;
    const int n0 = (tile & 63) << 6;
    const int tid = threadIdx.x;
    const int w = tid >> 5, lane = tid & 31;
    const int wm = w >> 1, wn = w & 1;
    const int g = lane >> 2, t = lane & 3;

    #pragma unroll
    for (int i = 0; i < 4; ++i) {
        int idx = tid + i*256;
        int n = idx >> 4, sg = idx & 15;
        cp16(&Xs[n*XSTR + sg*8], g_Xh + ((size_t)b*Nn + n0 + n)*Cch + sg*8);
    }
    #pragma unroll
    for (int i = 0; i < 2; ++i) {
        int idx = tid + i*256;
        int o = idx >> 2, sg = idx & 3;
        cp16(&Ws[0][o*WSTR + sg*8], g_Wh + o*Cch + sg*8);
    }
    cp_commit();

    float acc[2][4][4];
    for (int s = 0; s < 12; ++s) {
        const int p = s >> 2, kc4 = s & 3, buf = s & 1;
        cp_wait0();
        __syncthreads();
        if (s < 11) {
            const int p2 = (s+1) >> 2, kc2 = (s+1) & 3;
            const __half* src = g_Wh + (size_t)p2*Cch*Cch + kc2*32;
            #pragma unroll
            for (int i = 0; i < 2; ++i) {
                int idx = tid + i*256;
                int o = idx >> 2, sg = idx & 3;
                cp16(&Ws[buf^1][o*WSTR + sg*8], src + (size_t)o*Cch + sg*8);
            }
            cp_commit();
        }

        if (kc4 == 0) {
            const float* bias = (p==0) ? bq : (p==1) ? bk : bv;
            #pragma unroll
            for (int mi = 0; mi < 2; ++mi) {
                float blo = bias[wm*32 + mi*16 + g];
                float bhi = bias[wm*32 + mi*16 + 8 + g];
                #pragma unroll
                for (int n8 = 0; n8 < 4; ++n8) {
                    acc[mi][n8][0] = blo; acc[mi][n8][1] = blo;
                    acc[mi][n8][2] = bhi; acc[mi][n8][3] = bhi;
                }
            }
        }

        #pragma unroll
        for (int k2 = 0; k2 < 2; ++k2) {
            uint32_t af[2][4], bf[2][4];
            #pragma unroll
            for (int mi = 0; mi < 2; ++mi)
                ldmx4(af[mi], &Ws[buf][(wm*32 + mi*16 + (lane&15))*WSTR
                                       + k2*16 + (lane>>4)*8]);
            #pragma unroll
            for (int pr = 0; pr < 2; ++pr)
                ldmx4(bf[pr], &Xs[(wn*32 + pr*16 + (lane>>4)*8 + (lane&7))*XSTR
                                  + kc4*32 + k2*16 + ((lane>>3)&1)*8]);
            #pragma unroll
            for (int mi = 0; mi < 2; ++mi)
                #pragma unroll
                for (int pr = 0; pr < 2; ++pr)
                    #pragma unroll
                    for (int sb = 0; sb < 2; ++sb)
                        mmaf16(acc[mi][pr*2+sb][0], acc[mi][pr*2+sb][1],
                               acc[mi][pr*2+sb][2], acc[mi][pr*2+sb][3],
                               af[mi][0],af[mi][1],af[mi][2],af[mi][3],
                               bf[pr][sb*2], bf[pr][sb*2+1]);
        }

        if (kc4 == 3) {
            const size_t bh = (size_t)b*NH + wm;
            if (p < 2) {
                // Q scaled by QSCALE*16 (e4m3 normal range); K unscaled.
                const float sc8 = (p==0) ? (QSCALE * 16.0f) : 1.0f;
                unsigned char* tgt = (p==0) ? g_Qf8 : g_Kf8;
                #pragma unroll
                for (int mi = 0; mi < 2; ++mi) {
                    int dlo = mi*16 + g, dhi = dlo + 8;
                    #pragma unroll
                    for (int n8 = 0; n8 < 4; ++n8) {
                        int n = n0 + wn*32 + n8*8 + 2*t;
                        tgt[(bh*Nn + n  )*Dd + dlo] = f2e4m3(acc[mi][n8][0]*sc8);
                        tgt[(bh*Nn + n+1)*Dd + dlo] = f2e4m3(acc[mi][n8][1]*sc8);
                        tgt[(bh*Nn + n  )*Dd + dhi] = f2e4m3(acc[mi][n8][2]*sc8);
                        tgt[(bh*Nn + n+1)*Dd + dhi] = f2e4m3(acc[mi][n8][3]*sc8);
                    }
                }
            } else {
                #pragma unroll
                for (int mi = 0; mi < 2; ++mi) {
                    int dlo = mi*16 + g, dhi = dlo + 8;
                    #pragma unroll
                    for (int n8 = 0; n8 < 4; ++n8) {
                        int n = n0 + wn*32 + n8*8 + 2*t;
                        *(half2*)&g_Vt[(bh*Dd + dlo)*Nn + n] =
                            __floats2half2_rn(acc[mi][n8][0], acc[mi][n8][1]);
                        *(half2*)&g_Vt[(bh*Dd + dhi)*Nn + n] =
                            __floats2half2_rn(acc[mi][n8][2], acc[mi][n8][3]);
                    }
                }
            }
        }
    }
}

// ===========================================================================
// Kernel 2: flash attention.  S-GEMM via FP8 mma (m16n8k32, k=32 = full d):
// one mma per 16x8 S-tile.  Q/K fragments via plain LDS.32 from 48B-padded
// fp8 rows (conflict-free: word idx 12g+t distinct mod 32).  PV + row-sum
// mma + epilogue identical to the proven f16 path.
// ===========================================================================
#define VSTR 136
#define QROW 48
__global__ __launch_bounds__(256, 2) void attn_kernel()
{
    __shared__ __align__(16) unsigned char Qs8[256*QROW];     // 12 KB
    __shared__ __align__(16) unsigned char Ks8[2][128*QROW];  // 12 KB
    __shared__ __align__(16) __half VTs[2][32*VSTR];          // 17 KB

    const int bh  = blockIdx.y;
    const int q0  = blockIdx.x * 256;
    const int tid = threadIdx.x;
    const int w = tid >> 5, lane = tid & 31;
    const int g = lane >> 2, t = lane & 3;
    const int b = bh >> 2, h = bh & 3;

    const unsigned char* Kb8 = g_Kf8 + (size_t)bh*Nn*Dd;
    const __half* Vbase = g_Vt + (size_t)bh*Dd*Nn;

    // Preamble: Q (fp8) + K/V tile 0 in one group
    {
        const unsigned char* gq = g_Qf8 + ((size_t)bh*Nn + q0)*Dd;
        #pragma unroll
        for (int i = 0; i < 2; ++i) {
            int idx = tid + i*256;             // 512 cp16 (256 rows x 32B)
            int r = idx >> 1, c = idx & 1;
            cp16(&Qs8[r*QROW + c*16], gq + (size_t)r*Dd + c*16);
        }
        {                                      // K: 256 cp16 (128 rows x 32B)
            int r = tid >> 1, c = tid & 1;
            cp16(&Ks8[0][r*QROW + c*16], Kb8 + (size_t)r*Dd + c*16);
        }
        #pragma unroll
        for (int i = 0; i < 2; ++i) {          // V rows 0-31 x 128 keys
            int idx = tid + i*256;
            int d = idx >> 4, nb = idx & 15;
            cp16(&VTs[0][d*VSTR + nb*8], Vbase + (size_t)d*Nn + nb*8);
        }
        cp_commit();
    }
    cp_wait0();
    __syncthreads();

    // Q fp8 A-frags: per mi (m16 block): a0..a3 = words (g,t),(g+8,t),(g,t+4),(g+8,t+4)
    uint32_t qa8[2][4];
    #pragma unroll
    for (int mi = 0; mi < 2; ++mi) {
        int r0 = (w*32 + mi*16 + g)*QROW;
        int r1 = r0 + 8*QROW;
        qa8[mi][0] = *(const uint32_t*)&Qs8[r0 + t*4];
        qa8[mi][1] = *(const uint32_t*)&Qs8[r1 + t*4];
        qa8[mi][2] = *(const uint32_t*)&Qs8[r0 + 16 + t*4];
        qa8[mi][3] = *(const uint32_t*)&Qs8[r1 + 16 + t*4];
    }

    float oacc[2][4][4];
    float osum[2][4];
    #pragma unroll
    for (int mi = 0; mi < 2; ++mi) {
        #pragma unroll
        for (int n8 = 0; n8 < 4; ++n8)
            #pragma unroll
            for (int i = 0; i < 4; ++i) oacc[mi][n8][i] = 0.f;
        #pragma unroll
        for (int i = 0; i < 4; ++i) osum[mi][i] = 0.f;
    }

    // Ones B-frag for row-sum mma; exp2 descale (Q was scaled by 16)
    const uint32_t bs = (g == 0) ? 0x3C003C00u : 0u;
    const __half2 hsc = __float2half2_rn(0.0625f);

    for (int it = 0; it < Nn/128; ++it) {
        const int p = it & 1;
        if (it > 0) {
            cp_wait0();
            __syncthreads();
        }
        if (it < Nn/128 - 1) {
            const int k0n = (it+1) * 128;
            {
                int r = tid >> 1, c = tid & 1;
                cp16(&Ks8[p^1][r*QROW + c*16], Kb8 + (size_t)(k0n + r)*Dd + c*16);
            }
            #pragma unroll
            for (int i = 0; i < 2; ++i) {
                int idx = tid + i*256;
                int d = idx >> 4, nb = idx & 15;
                cp16(&VTs[p^1][d*VSTR + nb*8], Vbase + (size_t)d*Nn + k0n + nb*8);
            }
            cp_commit();
        }

        #pragma unroll
        for (int kc = 0; kc < 8; ++kc) {       // 16 keys per chunk
            // --- S via fp8 mma (2 n8-tiles, each k=32 full d) ---
            const unsigned char* kb = Ks8[p];
            int rA = (kc*16 + g)*QROW;
            int rB = rA + 8*QROW;
            uint32_t bA0 = *(const uint32_t*)&kb[rA + t*4];
            uint32_t bA1 = *(const uint32_t*)&kb[rA + 16 + t*4];
            uint32_t bB0 = *(const uint32_t*)&kb[rB + t*4];
            uint32_t bB1 = *(const uint32_t*)&kb[rB + 16 + t*4];
            uint32_t pa[2][4];
            #pragma unroll
            for (int mi = 0; mi < 2; ++mi) {
                float c0=0.f,c1=0.f,c2=0.f,c3=0.f;
                mmaf8(c0,c1,c2,c3, qa8[mi][0],qa8[mi][1],qa8[mi][2],qa8[mi][3],
                      bA0,bA1);
                float d0=0.f,d1=0.f,d2=0.f,d3=0.f;
                mmaf8(d0,d1,d2,d3, qa8[mi][0],qa8[mi][1],qa8[mi][2],qa8[mi][3],
                      bB0,bB1);
                pa[mi][0] = h2u(h2exp2(__hmul2(__floats2half2_rn(c0,c1), hsc)));
                pa[mi][1] = h2u(h2exp2(__hmul2(__floats2half2_rn(c2,c3), hsc)));
                pa[mi][2] = h2u(h2exp2(__hmul2(__floats2half2_rn(d0,d1), hsc)));
                pa[mi][3] = h2u(h2exp2(__hmul2(__floats2half2_rn(d2,d3), hsc)));
            }
            // --- V frags, then O += P V (+ row sum) ---
            uint32_t vb[4][2];
            #pragma unroll
            for (int n8 = 0; n8 < 4; ++n8)
                ldmx2(vb[n8], &VTs[p][(n8*8 + (lane&7))*VSTR
                                      + kc*16 + ((lane>>3)&1)*8]);
            #pragma unroll
            for (int mi = 0; mi < 2; ++mi) {
                #pragma unroll
                for (int n8 = 0; n8 < 4; ++n8)
                    mmaf16(oacc[mi][n8][0],oacc[mi][n8][1],
                           oacc[mi][n8][2],oacc[mi][n8][3],
                           pa[mi][0],pa[mi][1],pa[mi][2],pa[mi][3],
                           vb[n8][0], vb[n8][1]);
                mmaf16(osum[mi][0],osum[mi][1],osum[mi][2],osum[mi][3],
                       pa[mi][0],pa[mi][1],pa[mi][2],pa[mi][3], bs, bs);
            }
        }
    }

    // Normalize and store to (b, n, c) f16 token-major
    #pragma unroll
    for (int mi = 0; mi < 2; ++mi) {
        float invg  = 1.f / __shfl_sync(0xffffffffu, osum[mi][0], lane & ~3);
        float invg8 = 1.f / __shfl_sync(0xffffffffu, osum[mi][2], lane & ~3);
        int nlo = q0 + w*32 + mi*16 + g;
        __half* rowlo = g_attnh + ((size_t)b*Nn + nlo    )*Cch + h*Dd;
        __half* rowhi = g_attnh + ((size_t)b*Nn + nlo + 8)*Cch + h*Dd;
        #pragma unroll
        for (int n8 = 0; n8 < 4; ++n8) {
            int d = n8*8 + 2*t;
            *(half2*)(rowlo + d) = __floats2half2_rn(oacc[mi][n8][0]*invg,
                                                     oacc[mi][n8][1]*invg);
            *(half2*)(rowhi + d) = __floats2half2_rn(oacc[mi][n8][2]*invg8,
                                                     oacc[mi][n8][3]*invg8);
        }
    }
}

// ===========================================================================
// Kernel 3: output projection + residual, cp.async pipelined f16 mma.
// ===========================================================================
__global__ __launch_bounds__(256, 2) void oproj_kernel(
    const float* __restrict__ x,
    const float* __restrict__ bo,
    float* __restrict__ out)
{
    __shared__ __align__(16) __half As[64*XSTR];
    __shared__ __align__(16) __half Ws[2][128*WSTR];

    const int tile = blockIdx.x;
    const int b  = tile >> 6;
    const int n0 = (tile & 63) << 6;
    const int tid = threadIdx.x;
    const int w = tid >> 5, lane = tid & 31;
    const int wm = w >> 1, wn = w & 1;
    const int g = lane >> 2, t = lane & 3;

    const __half* Wo = g_Wh + (size_t)3*Cch*Cch;

    #pragma unroll
    for (int i = 0; i < 4; ++i) {
        int idx = tid + i*256;
        int n = idx >> 4, sg = idx & 15;
        cp16(&As[n*XSTR + sg*8], g_attnh + ((size_t)b*Nn + n0 + n)*Cch + sg*8);
    }
    #pragma unroll
    for (int i = 0; i < 2; ++i) {
        int idx = tid + i*256;
        int o = idx >> 2, sg = idx & 3;
        cp16(&Ws[0][o*WSTR + sg*8], Wo + (size_t)o*Cch + sg*8);
    }
    cp_commit();

    float acc[2][4][4];
    #pragma unroll
    for (int mi = 0; mi < 2; ++mi) {
        float blo = bo[wm*32 + mi*16 + g];
        float bhi = bo[wm*32 + mi*16 + 8 + g];
        #pragma unroll
        for (int n8 = 0; n8 < 4; ++n8) {
            acc[mi][n8][0] = blo; acc[mi][n8][1] = blo;
            acc[mi][n8][2] = bhi; acc[mi][n8][3] = bhi;
        }
    }

    for (int s = 0; s < 4; ++s) {
        const int buf = s & 1;
        cp_wait0();
        __syncthreads();
        if (s < 3) {
            const __half* src = Wo + (s+1)*32;
            #pragma unroll
            for (int i = 0; i < 2; ++i) {
                int idx = tid + i*256;
                int o = idx >> 2, sg = idx & 3;
                cp16(&Ws[buf^1][o*WSTR + sg*8], src + (size_t)o*Cch + sg*8);
            }
            cp_commit();
        }

        #pragma unroll
        for (int k2 = 0; k2 < 2; ++k2) {
            uint32_t af[2][4], bf[2][4];
            #pragma unroll
            for (int mi = 0; mi < 2; ++mi)
                ldmx4(af[mi], &Ws[buf][(wm*32 + mi*16 + (lane&15))*WSTR
                                       + k2*16 + (lane>>4)*8]);
            #pragma unroll
            for (int pr = 0; pr < 2; ++pr)
                ldmx4(bf[pr], &As[(wn*32 + pr*16 + (lane>>4)*8 + (lane&7))*XSTR
                                  + s*32 + k2*16 + ((lane>>3)&1)*8]);
            #pragma unroll
            for (int mi = 0; mi < 2; ++mi)
                #pragma unroll
                for (int pr = 0; pr < 2; ++pr)
                    #pragma unroll
                    for (int sb = 0; sb < 2; ++sb)
                        mmaf16(acc[mi][pr*2+sb][0], acc[mi][pr*2+sb][1],
                               acc[mi][pr*2+sb][2], acc[mi][pr*2+sb][3],
                               af[mi][0],af[mi][1],af[mi][2],af[mi][3],
                               bf[pr][sb*2], bf[pr][sb*2+1]);
        }
    }

    #pragma unroll
    for (int mi = 0; mi < 2; ++mi) {
        int olo = wm*32 + mi*16 + g, ohi = olo + 8;
        #pragma unroll
        for (int n8 = 0; n8 < 4; ++n8) {
            int n = n0 + wn*32 + n8*8 + 2*t;
            size_t ilo = ((size_t)b*Cch + olo)*Nn + n;
            size_t ihi = ((size_t)b*Cch + ohi)*Nn + n;
            float2 xlo = *(const float2*)(x + ilo);
            float2 xhi = *(const float2*)(x + ihi);
            float2 r0; r0.x = xlo.x + acc[mi][n8][0]; r0.y = xlo.y + acc[mi][n8][1];
            float2 r1; r1.x = xhi.x + acc[mi][n8][2]; r1.y = xhi.y + acc[mi][n8][3];
            *(float2*)(out + ilo) = r0;
            *(float2*)(out + ihi) = r1;
        }
    }
}

// ---------------------------------------------------------------------------
extern "C" void kernel_launch(void* const* d_in, const int* in_sizes, int n_in,
                              void* d_out, int out_size)
{
    const float* x  = (const float*)d_in[0];
    const float* wq = (const float*)d_in[1];
    const float* bq = (const float*)d_in[2];
    const float* wk = (const float*)d_in[3];
    const float* bk = (const float*)d_in[4];
    const float* wv = (const float*)d_in[5];
    const float* bv = (const float*)d_in[6];
    const float* wo = (const float*)d_in[7];
    const float* bo = (const float*)d_in[8];
    float* out = (float*)d_out;

    prep_kernel<<<544, 256>>>(x, wq, wk, wv, wo);
    qkv_kernel<<<Bsz*(Nn/64), 256>>>(bq, bk, bv);
    attn_kernel<<<dim3(Nn/256, Bsz*NH), 256>>>();
    oproj_kernel<<<Bsz*(Nn/64), 256>>>(x, bo, out);
}

// round 15
// speedup vs baseline: 1.7770x; 1.7770x over previous
#include <cuda_runtime.h>
#include <cuda_fp16.h>
#include <stdint.h>
#include <math.h>

// Problem constants
#define Bsz 4
#define Cch 128
#define Nn 4096
#define NH 4
#define Dd 32
// 1/sqrt(32) * log2(e): fold softmax scale AND exp2 conversion into Q
#define QSCALE (0.17677669529663687f * 1.4426950408889634f)

// Scratch (__device__ globals; allocation-free rule)
__device__ __half g_Wh[4*Cch*Cch];        // wq,wk,wv,wo as f16 (o, c)
__device__ __half g_Xh[Bsz*Nn*Cch];       // x transposed to (b, n, c) f16
__device__ __half g_Q[Bsz*NH*Nn*Dd];      // (bh, n, d), pre-scaled by QSCALE
__device__ __half g_K[Bsz*NH*Nn*Dd];      // (bh, n, d)
__device__ __half g_Vt[Bsz*NH*Dd*Nn];     // (bh, d, n)
__device__ __half g_attnh[Bsz*Nn*Cch];    // (b, n, c) token-major

// ---------------------------------------------------------------------------
__device__ __forceinline__ void mmaf16(float&c0,float&c1,float&c2,float&c3,
    uint32_t a0,uint32_t a1,uint32_t a2,uint32_t a3,uint32_t b0,uint32_t b1)
{
    asm volatile("mma.sync.aligned.m16n8k16.row.col.f32.f16.f16.f32 "
        "{%0,%1,%2,%3},{%4,%5,%6,%7},{%8,%9},{%0,%1,%2,%3};"
        : "+f"(c0),"+f"(c1),"+f"(c2),"+f"(c3)
        : "r"(a0),"r"(a1),"r"(a2),"r"(a3),"r"(b0),"r"(b1));
}
// f16 accumulator variant: D/C are 2x .b32 (4 f16).  D is directly usable as
// an A-fragment of the next mma and as h2exp2 input — no packing needed.
__device__ __forceinline__ void mmah16(uint32_t&c0,uint32_t&c1,
    uint32_t a0,uint32_t a1,uint32_t a2,uint32_t a3,uint32_t b0,uint32_t b1)
{
    asm volatile("mma.sync.aligned.m16n8k16.row.col.f16.f16.f16.f16 "
        "{%0,%1},{%2,%3,%4,%5},{%6,%7},{%0,%1};"
        : "+r"(c0),"+r"(c1)
        : "r"(a0),"r"(a1),"r"(a2),"r"(a3),"r"(b0),"r"(b1));
}
__device__ __forceinline__ void ldmx4(uint32_t* r, const void* p) {
    uint32_t a = (uint32_t)__cvta_generic_to_shared(p);
    asm volatile("ldmatrix.sync.aligned.m8n8.x4.shared.b16 {%0,%1,%2,%3}, [%4];"
        : "=r"(r[0]),"=r"(r[1]),"=r"(r[2]),"=r"(r[3]) : "r"(a));
}
__device__ __forceinline__ void ldmx2(uint32_t* r, const void* p) {
    uint32_t a = (uint32_t)__cvta_generic_to_shared(p);
    asm volatile("ldmatrix.sync.aligned.m8n8.x2.shared.b16 {%0,%1}, [%2];"
        : "=r"(r[0]),"=r"(r[1]) : "r"(a));
}
__device__ __forceinline__ void cp16(void* smem, const void* g) {
    uint32_t a = (uint32_t)__cvta_generic_to_shared(smem);
    asm volatile("cp.async.ca.shared.global [%0], [%1], 16;" :: "r"(a), "l"(g));
}
__device__ __forceinline__ void cp_commit() {
    asm volatile("cp.async.commit_group;");
}
__device__ __forceinline__ void cp_wait0() {
    asm volatile("cp.async.wait_group 0;" ::: "memory");
}
__device__ __forceinline__ uint32_t h2u(__half2 h) { return *(uint32_t*)&h; }
__device__ __forceinline__ __half2 u2h(uint32_t u) { return *(__half2*)&u; }

// ===========================================================================
// Kernel 0: prep — W -> f16, x -> f16 transposed (b, n, c).  Fat blocks.
// ===========================================================================
__global__ __launch_bounds__(256) void prep_kernel(
    const float* __restrict__ x,
    const float* __restrict__ wq, const float* __restrict__ wk,
    const float* __restrict__ wv, const float* __restrict__ wo)
{
    const int bid = blockIdx.x;
    const int tid = threadIdx.x;
    if (bid < 512) {
        __shared__ float tile[64][65];
        const int b  = bid >> 7;
        const int c0 = ((bid >> 6) & 1) * 64;
        const int n0 = (bid & 63) * 64;
        #pragma unroll
        for (int i = 0; i < 16; ++i) {
            int idx = tid + i*256;
            int c = idx >> 6, n = idx & 63;
            tile[c][n] = x[((size_t)b*Cch + c0 + c)*Nn + n0 + n];
        }
        __syncthreads();
        #pragma unroll
        for (int i = 0; i < 8; ++i) {
            int idx = tid + i*256;
            int n = idx >> 5, cp = idx & 31;
            int c = cp*2;
            *(half2*)&g_Xh[((size_t)b*Nn + n0 + n)*Cch + c0 + c] =
                __floats2half2_rn(tile[c][n], tile[c+1][n]);
        }
    } else {
        const int wb = bid - 512;
        #pragma unroll
        for (int i = 0; i < 8; ++i) {
            int idx = wb*2048 + i*256 + tid;
            int m = idx >> 14, rr = idx & 16383;
            const float* W = (m==0) ? wq : (m==1) ? wk : (m==2) ? wv : wo;
            g_Wh[idx] = __float2half(W[rr]);
        }
    }
}

// ===========================================================================
// Kernel 1: fused QKV projection, cp.async double-buffered f16 pipeline.
// ===========================================================================
#define XSTR 136
#define WSTR 40
__global__ __launch_bounds__(256, 2) void qkv_kernel(
    const float* __restrict__ bq, const float* __restrict__ bk,
    const float* __restrict__ bv)
{
    __shared__ __align__(16) __half Xs[64*XSTR];
    __shared__ __align__(16) __half Ws[2][128*WSTR];

    const int tile = blockIdx.x;
    const int b  = tile >> 6;
    const int n0 = (tile & 63) << 6;
    const int tid = threadIdx.x;
    const int w = tid >> 5, lane = tid & 31;
    const int wm = w >> 1, wn = w & 1;
    const int g = lane >> 2, t = lane & 3;

    #pragma unroll
    for (int i = 0; i < 4; ++i) {
        int idx = tid + i*256;
        int n = idx >> 4, sg = idx & 15;
        cp16(&Xs[n*XSTR + sg*8], g_Xh + ((size_t)b*Nn + n0 + n)*Cch + sg*8);
    }
    #pragma unroll
    for (int i = 0; i < 2; ++i) {
        int idx = tid + i*256;
        int o = idx >> 2, sg = idx & 3;
        cp16(&Ws[0][o*WSTR + sg*8], g_Wh + o*Cch + sg*8);
    }
    cp_commit();

    float acc[2][4][4];
    for (int s = 0; s < 12; ++s) {
        const int p = s >> 2, kc4 = s & 3, buf = s & 1;
        cp_wait0();
        __syncthreads();
        if (s < 11) {
            const int p2 = (s+1) >> 2, kc2 = (s+1) & 3;
            const __half* src = g_Wh + (size_t)p2*Cch*Cch + kc2*32;
            #pragma unroll
            for (int i = 0; i < 2; ++i) {
                int idx = tid + i*256;
                int o = idx >> 2, sg = idx & 3;
                cp16(&Ws[buf^1][o*WSTR + sg*8], src + (size_t)o*Cch + sg*8);
            }
            cp_commit();
        }

        if (kc4 == 0) {
            const float* bias = (p==0) ? bq : (p==1) ? bk : bv;
            #pragma unroll
            for (int mi = 0; mi < 2; ++mi) {
                float blo = bias[wm*32 + mi*16 + g];
                float bhi = bias[wm*32 + mi*16 + 8 + g];
                #pragma unroll
                for (int n8 = 0; n8 < 4; ++n8) {
                    acc[mi][n8][0] = blo; acc[mi][n8][1] = blo;
                    acc[mi][n8][2] = bhi; acc[mi][n8][3] = bhi;
                }
            }
        }

        #pragma unroll
        for (int k2 = 0; k2 < 2; ++k2) {
            uint32_t af[2][4], bf[2][4];
            #pragma unroll
            for (int mi = 0; mi < 2; ++mi)
                ldmx4(af[mi], &Ws[buf][(wm*32 + mi*16 + (lane&15))*WSTR
                                       + k2*16 + (lane>>4)*8]);
            #pragma unroll
            for (int pr = 0; pr < 2; ++pr)
                ldmx4(bf[pr], &Xs[(wn*32 + pr*16 + (lane>>4)*8 + (lane&7))*XSTR
                                  + kc4*32 + k2*16 + ((lane>>3)&1)*8]);
            #pragma unroll
            for (int mi = 0; mi < 2; ++mi)
                #pragma unroll
                for (int pr = 0; pr < 2; ++pr)
                    #pragma unroll
                    for (int sb = 0; sb < 2; ++sb)
                        mmaf16(acc[mi][pr*2+sb][0], acc[mi][pr*2+sb][1],
                               acc[mi][pr*2+sb][2], acc[mi][pr*2+sb][3],
                               af[mi][0],af[mi][1],af[mi][2],af[mi][3],
                               bf[pr][sb*2], bf[pr][sb*2+1]);
        }

        if (kc4 == 3) {
            const float sc = (p==0) ? QSCALE : 1.0f;
            const size_t bh = (size_t)b*NH + wm;
            #pragma unroll
            for (int mi = 0; mi < 2; ++mi) {
                int dlo = mi*16 + g, dhi = dlo + 8;
                #pragma unroll
                for (int n8 = 0; n8 < 4; ++n8) {
                    int n = n0 + wn*32 + n8*8 + 2*t;
                    if (p < 2) {
                        __half* tgt = (p==0) ? g_Q : g_K;
                        tgt[(bh*Nn + n  )*Dd + dlo] = __float2half(acc[mi][n8][0]*sc);
                        tgt[(bh*Nn + n+1)*Dd + dlo] = __float2half(acc[mi][n8][1]*sc);
                        tgt[(bh*Nn + n  )*Dd + dhi] = __float2half(acc[mi][n8][2]*sc);
                        tgt[(bh*Nn + n+1)*Dd + dhi] = __float2half(acc[mi][n8][3]*sc);
                    } else {
                        *(half2*)&g_Vt[(bh*Dd + dlo)*Nn + n] =
                            __floats2half2_rn(acc[mi][n8][0], acc[mi][n8][1]);
                        *(half2*)&g_Vt[(bh*Dd + dhi)*Nn + n] =
                            __floats2half2_rn(acc[mi][n8][2], acc[mi][n8][3]);
                    }
                }
            }
        }
    }
}

// ===========================================================================
// Kernel 2: flash attention.  S-GEMM with f16 accumulators (mma output IS the
// h2exp2 input AND the PV A-fragment).  Row-sums on the fma pipe via HADD2
// (tile-local f16 partials, flushed to f32 per 128-key tile) — frees the
// tensor pipe of the ones-mma (2 of 18 HMMA per chunk).
// ===========================================================================
#define KSTR 40
#define VSTR 136
__global__ __launch_bounds__(256, 2) void attn_kernel()
{
    __shared__ __align__(16) __half Qs[256*KSTR];      // 20.0 KB
    __shared__ __align__(16) __half Ks[2][128*KSTR];   // 20.0 KB
    __shared__ __align__(16) __half VTs[2][32*VSTR];   // 17.0 KB

    const int bh  = blockIdx.y;
    const int q0  = blockIdx.x * 256;
    const int tid = threadIdx.x;
    const int w = tid >> 5, lane = tid & 31;
    const int g = lane >> 2, t = lane & 3;
    const int b = bh >> 2, h = bh & 3;

    const __half* Kbase = g_K  + (size_t)bh*Nn*Dd;
    const __half* Vbase = g_Vt + (size_t)bh*Dd*Nn;

    // Preamble: Q tile + K/V tile 0 in one group
    {
        const __half* gq = g_Q + ((size_t)bh*Nn + q0)*Dd;
        #pragma unroll
        for (int i = 0; i < 4; ++i) {
            int idx = tid + i*256;             // 1024 cp16
            int r = idx >> 2, sg = idx & 3;
            cp16(&Qs[r*KSTR + sg*8], gq + (size_t)r*Dd + sg*8);
        }
        #pragma unroll
        for (int i = 0; i < 2; ++i) {          // K: 512 cp16 (128 rows x 64B)
            int idx = tid + i*256;
            int n = idx >> 2, sg = idx & 3;
            cp16(&Ks[0][n*KSTR + sg*8], Kbase + (size_t)n*Dd + sg*8);
        }
        #pragma unroll
        for (int i = 0; i < 2; ++i) {          // V: 512 cp16 (32 rows x 256B)
            int idx = tid + i*256;
            int d = idx >> 4, nb = idx & 15;
            cp16(&VTs[0][d*VSTR + nb*8], Vbase + (size_t)d*Nn + nb*8);
        }
        cp_commit();
    }
    cp_wait0();
    __syncthreads();

    // Q a-frags: 32 rows per warp, 2 m16 x 2 k16
    uint32_t qa[2][2][4];
    #pragma unroll
    for (int mi = 0; mi < 2; ++mi)
        #pragma unroll
        for (int kc = 0; kc < 2; ++kc)
            ldmx4(qa[mi][kc], &Qs[(w*32 + mi*16 + (lane&15))*KSTR
                                  + kc*16 + (lane>>4)*8]);

    float oacc[2][4][4];
    float fsum[2][2];                          // f32 row sums (rows g, g+8)
    #pragma unroll
    for (int mi = 0; mi < 2; ++mi) {
        #pragma unroll
        for (int n8 = 0; n8 < 4; ++n8)
            #pragma unroll
            for (int i = 0; i < 4; ++i) oacc[mi][n8][i] = 0.f;
        fsum[mi][0] = 0.f; fsum[mi][1] = 0.f;
    }

    for (int it = 0; it < Nn/128; ++it) {
        const int p = it & 1;
        if (it > 0) {
            cp_wait0();
            __syncthreads();
        }
        if (it < Nn/128 - 1) {
            const int k0n = (it+1) * 128;
            #pragma unroll
            for (int i = 0; i < 2; ++i) {
                int idx = tid + i*256;
                int n = idx >> 2, sg = idx & 3;
                cp16(&Ks[p^1][n*KSTR + sg*8], Kbase + (size_t)(k0n + n)*Dd + sg*8);
            }
            #pragma unroll
            for (int i = 0; i < 2; ++i) {
                int idx = tid + i*256;
                int d = idx >> 4, nb = idx & 15;
                cp16(&VTs[p^1][d*VSTR + nb*8], Vbase + (size_t)d*Nn + k0n + nb*8);
            }
            cp_commit();
        }

        // Tile-local f16 row-sum partials (magnitude <= ~30, safe in f16)
        __half2 tsum[2][2];
        tsum[0][0] = tsum[0][1] = tsum[1][0] = tsum[1][1] =
            __floats2half2_rn(0.f, 0.f);

        #pragma unroll
        for (int kc = 0; kc < 8; ++kc) {       // 16 keys per chunk
            // --- S (f16 accum) for keys kc*16..kc*16+15, exp2 in place ---
            uint32_t kb0[4], kb1[4];
            ldmx4(kb0, &Ks[p][((kc*2  )*8 + (lane&7))*KSTR + (lane>>3)*8]);
            ldmx4(kb1, &Ks[p][((kc*2+1)*8 + (lane&7))*KSTR + (lane>>3)*8]);
            uint32_t pa[2][4];
            #pragma unroll
            for (int mi = 0; mi < 2; ++mi) {
                uint32_t c0=0,c1=0,d0=0,d1=0;
                mmah16(c0,c1, qa[mi][0][0],qa[mi][0][1],qa[mi][0][2],qa[mi][0][3],
                       kb0[0],kb0[1]);
                mmah16(c0,c1, qa[mi][1][0],qa[mi][1][1],qa[mi][1][2],qa[mi][1][3],
                       kb0[2],kb0[3]);
                mmah16(d0,d1, qa[mi][0][0],qa[mi][0][1],qa[mi][0][2],qa[mi][0][3],
                       kb1[0],kb1[1]);
                mmah16(d0,d1, qa[mi][1][0],qa[mi][1][1],qa[mi][1][2],qa[mi][1][3],
                       kb1[2],kb1[3]);
                // exp2 directly on the f16x2 accumulators -> PV A-fragments
                pa[mi][0] = h2u(h2exp2(u2h(c0)));
                pa[mi][1] = h2u(h2exp2(u2h(c1)));
                pa[mi][2] = h2u(h2exp2(u2h(d0)));
                pa[mi][3] = h2u(h2exp2(u2h(d1)));
                // row-sum partials on the fma pipe (row g: pa0+pa2, g+8: pa1+pa3)
                tsum[mi][0] = __hadd2(tsum[mi][0],
                                      __hadd2(u2h(pa[mi][0]), u2h(pa[mi][2])));
                tsum[mi][1] = __hadd2(tsum[mi][1],
                                      __hadd2(u2h(pa[mi][1]), u2h(pa[mi][3])));
            }
            // --- V frags, then O += P V ---
            uint32_t vb[4][2];
            #pragma unroll
            for (int n8 = 0; n8 < 4; ++n8)
                ldmx2(vb[n8], &VTs[p][(n8*8 + (lane&7))*VSTR
                                      + kc*16 + ((lane>>3)&1)*8]);
            #pragma unroll
            for (int mi = 0; mi < 2; ++mi) {
                #pragma unroll
                for (int n8 = 0; n8 < 4; ++n8)
                    mmaf16(oacc[mi][n8][0],oacc[mi][n8][1],
                           oacc[mi][n8][2],oacc[mi][n8][3],
                           pa[mi][0],pa[mi][1],pa[mi][2],pa[mi][3],
                           vb[n8][0], vb[n8][1]);
            }
        }

        // Flush tile partials to f32
        #pragma unroll
        for (int mi = 0; mi < 2; ++mi) {
            float2 f0 = __half22float2(tsum[mi][0]);
            float2 f1 = __half22float2(tsum[mi][1]);
            fsum[mi][0] += f0.x + f0.y;
            fsum[mi][1] += f1.x + f1.y;
        }
    }

    // Normalize and store to (b, n, c) f16 token-major.
    // Reduce across the 4 t-lanes of each quad (they hold disjoint keys).
    #pragma unroll
    for (int mi = 0; mi < 2; ++mi) {
        float sg = fsum[mi][0];
        sg += __shfl_xor_sync(0xffffffffu, sg, 1);
        sg += __shfl_xor_sync(0xffffffffu, sg, 2);
        float sh = fsum[mi][1];
        sh += __shfl_xor_sync(0xffffffffu, sh, 1);
        sh += __shfl_xor_sync(0xffffffffu, sh, 2);
        float invg  = 1.f / sg;
        float invg8 = 1.f / sh;
        int nlo = q0 + w*32 + mi*16 + g;
        __half* rowlo = g_attnh + ((size_t)b*Nn + nlo    )*Cch + h*Dd;
        __half* rowhi = g_attnh + ((size_t)b*Nn + nlo + 8)*Cch + h*Dd;
        #pragma unroll
        for (int n8 = 0; n8 < 4; ++n8) {
            int d = n8*8 + 2*t;
            *(half2*)(rowlo + d) = __floats2half2_rn(oacc[mi][n8][0]*invg,
                                                     oacc[mi][n8][1]*invg);
            *(half2*)(rowhi + d) = __floats2half2_rn(oacc[mi][n8][2]*invg8,
                                                     oacc[mi][n8][3]*invg8);
        }
    }
}

// ===========================================================================
// Kernel 3: output projection + residual, cp.async pipelined f16 mma.
// ===========================================================================
__global__ __launch_bounds__(256, 2) void oproj_kernel(
    const float* __restrict__ x,
    const float* __restrict__ bo,
    float* __restrict__ out)
{
    __shared__ __align__(16) __half As[64*XSTR];
    __shared__ __align__(16) __half Ws[2][128*WSTR];

    const int tile = blockIdx.x;
    const int b  = tile >> 6;
    const int n0 = (tile & 63) << 6;
    const int tid = threadIdx.x;
    const int w = tid >> 5, lane = tid & 31;
    const int wm = w >> 1, wn = w & 1;
    const int g = lane >> 2, t = lane & 3;

    const __half* Wo = g_Wh + (size_t)3*Cch*Cch;

    #pragma unroll
    for (int i = 0; i < 4; ++i) {
        int idx = tid + i*256;
        int n = idx >> 4, sg = idx & 15;
        cp16(&As[n*XSTR + sg*8], g_attnh + ((size_t)b*Nn + n0 + n)*Cch + sg*8);
    }
    #pragma unroll
    for (int i = 0; i < 2; ++i) {
        int idx = tid + i*256;
        int o = idx >> 2, sg = idx & 3;
        cp16(&Ws[0][o*WSTR + sg*8], Wo + (size_t)o*Cch + sg*8);
    }
    cp_commit();

    float acc[2][4][4];
    #pragma unroll
    for (int mi = 0; mi < 2; ++mi) {
        float blo = bo[wm*32 + mi*16 + g];
        float bhi = bo[wm*32 + mi*16 + 8 + g];
        #pragma unroll
        for (int n8 = 0; n8 < 4; ++n8) {
            acc[mi][n8][0] = blo; acc[mi][n8][1] = blo;
            acc[mi][n8][2] = bhi; acc[mi][n8][3] = bhi;
        }
    }

    for (int s = 0; s < 4; ++s) {
        const int buf = s & 1;
        cp_wait0();
        __syncthreads();
        if (s < 3) {
            const __half* src = Wo + (s+1)*32;
            #pragma unroll
            for (int i = 0; i < 2; ++i) {
                int idx = tid + i*256;
                int o = idx >> 2, sg = idx & 3;
                cp16(&Ws[buf^1][o*WSTR + sg*8], src + (size_t)o*Cch + sg*8);
            }
            cp_commit();
        }

        #pragma unroll
        for (int k2 = 0; k2 < 2; ++k2) {
            uint32_t af[2][4], bf[2][4];
            #pragma unroll
            for (int mi = 0; mi < 2; ++mi)
                ldmx4(af[mi], &Ws[buf][(wm*32 + mi*16 + (lane&15))*WSTR
                                       + k2*16 + (lane>>4)*8]);
            #pragma unroll
            for (int pr = 0; pr < 2; ++pr)
                ldmx4(bf[pr], &As[(wn*32 + pr*16 + (lane>>4)*8 + (lane&7))*XSTR
                                  + s*32 + k2*16 + ((lane>>3)&1)*8]);
            #pragma unroll
            for (int mi = 0; mi < 2; ++mi)
                #pragma unroll
                for (int pr = 0; pr < 2; ++pr)
                    #pragma unroll
                    for (int sb = 0; sb < 2; ++sb)
                        mmaf16(acc[mi][pr*2+sb][0], acc[mi][pr*2+sb][1],
                               acc[mi][pr*2+sb][2], acc[mi][pr*2+sb][3],
                               af[mi][0],af[mi][1],af[mi][2],af[mi][3],
                               bf[pr][sb*2], bf[pr][sb*2+1]);
        }
    }

    #pragma unroll
    for (int mi = 0; mi < 2; ++mi) {
        int olo = wm*32 + mi*16 + g, ohi = olo + 8;
        #pragma unroll
        for (int n8 = 0; n8 < 4; ++n8) {
            int n = n0 + wn*32 + n8*8 + 2*t;
            size_t ilo = ((size_t)b*Cch + olo)*Nn + n;
            size_t ihi = ((size_t)b*Cch + ohi)*Nn + n;
            float2 xlo = *(const float2*)(x + ilo);
            float2 xhi = *(const float2*)(x + ihi);
            float2 r0; r0.x = xlo.x + acc[mi][n8][0]; r0.y = xlo.y + acc[mi][n8][1];
            float2 r1; r1.x = xhi.x + acc[mi][n8][2]; r1.y = xhi.y + acc[mi][n8][3];
            *(float2*)(out + ilo) = r0;
            *(float2*)(out + ihi) = r1;
        }
    }
}

// ---------------------------------------------------------------------------
extern "C" void kernel_launch(void* const* d_in, const int* in_sizes, int n_in,
                              void* d_out, int out_size)
{
    const float* x  = (const float*)d_in[0];
    const float* wq = (const float*)d_in[1];
    const float* bq = (const float*)d_in[2];
    const float* wk = (const float*)d_in[3];
    const float* bk = (const float*)d_in[4];
    const float* wv = (const float*)d_in[5];
    const float* bv = (const float*)d_in[6];
    const float* wo = (const float*)d_in[7];
    const float* bo = (const float*)d_in[8];
    float* out = (float*)d_out;

    prep_kernel<<<544, 256>>>(x, wq, wk, wv, wo);
    qkv_kernel<<<Bsz*(Nn/64), 256>>>(bq, bk, bv);
    attn_kernel<<<dim3(Nn/256, Bsz*NH), 256>>>();
    oproj_kernel<<<Bsz*(Nn/64), 256>>>(x, bo, out);
}

// round 16
// speedup vs baseline: 1.7922x; 1.0086x over previous
#include <cuda_runtime.h>
#include <cuda_fp16.h>
#include <stdint.h>
#include <math.h>

// Problem constants
#define Bsz 4
#define Cch 128
#define Nn 4096
#define NH 4
#define Dd 32
// 1/sqrt(32) * log2(e): fold softmax scale AND exp2 conversion into Q
#define QSCALE (0.17677669529663687f * 1.4426950408889634f)

// Scratch (__device__ globals; allocation-free rule)
__device__ __half g_Wh[4*Cch*Cch];        // wq,wk,wv,wo as f16 (o, c)
__device__ __half g_Q[Bsz*NH*Nn*Dd];      // (bh, n, d), pre-scaled by QSCALE
__device__ __half g_K[Bsz*NH*Nn*Dd];      // (bh, n, d)
__device__ __half g_Vt[Bsz*NH*Dd*Nn];     // (bh, d, n)
__device__ __half g_attnh[Bsz*Nn*Cch];    // (b, n, c) token-major

// ---------------------------------------------------------------------------
__device__ __forceinline__ void mmaf16(float&c0,float&c1,float&c2,float&c3,
    uint32_t a0,uint32_t a1,uint32_t a2,uint32_t a3,uint32_t b0,uint32_t b1)
{
    asm volatile("mma.sync.aligned.m16n8k16.row.col.f32.f16.f16.f32 "
        "{%0,%1,%2,%3},{%4,%5,%6,%7},{%8,%9},{%0,%1,%2,%3};"
        : "+f"(c0),"+f"(c1),"+f"(c2),"+f"(c3)
        : "r"(a0),"r"(a1),"r"(a2),"r"(a3),"r"(b0),"r"(b1));
}
// f16 accumulator variant: D/C are 2x .b32 (4 f16).  D is directly usable as
// an A-fragment of the next mma and as h2exp2 input — no packing needed.
__device__ __forceinline__ void mmah16(uint32_t&c0,uint32_t&c1,
    uint32_t a0,uint32_t a1,uint32_t a2,uint32_t a3,uint32_t b0,uint32_t b1)
{
    asm volatile("mma.sync.aligned.m16n8k16.row.col.f16.f16.f16.f16 "
        "{%0,%1},{%2,%3,%4,%5},{%6,%7},{%0,%1};"
        : "+r"(c0),"+r"(c1)
        : "r"(a0),"r"(a1),"r"(a2),"r"(a3),"r"(b0),"r"(b1));
}
__device__ __forceinline__ void ldmx4(uint32_t* r, const void* p) {
    uint32_t a = (uint32_t)__cvta_generic_to_shared(p);
    asm volatile("ldmatrix.sync.aligned.m8n8.x4.shared.b16 {%0,%1,%2,%3}, [%4];"
        : "=r"(r[0]),"=r"(r[1]),"=r"(r[2]),"=r"(r[3]) : "r"(a));
}
__device__ __forceinline__ void ldmx2(uint32_t* r, const void* p) {
    uint32_t a = (uint32_t)__cvta_generic_to_shared(p);
    asm volatile("ldmatrix.sync.aligned.m8n8.x2.shared.b16 {%0,%1}, [%2];"
        : "=r"(r[0]),"=r"(r[1]) : "r"(a));
}
__device__ __forceinline__ void cp16(void* smem, const void* g) {
    uint32_t a = (uint32_t)__cvta_generic_to_shared(smem);
    asm volatile("cp.async.ca.shared.global [%0], [%1], 16;" :: "r"(a), "l"(g));
}
__device__ __forceinline__ void cp_commit() {
    asm volatile("cp.async.commit_group;");
}
__device__ __forceinline__ void cp_wait0() {
    asm volatile("cp.async.wait_group 0;" ::: "memory");
}
__device__ __forceinline__ uint32_t h2u(__half2 h) { return *(uint32_t*)&h; }
__device__ __forceinline__ __half2 u2h(uint32_t u) { return *(__half2*)&u; }

// ===========================================================================
// Kernel 0: prep — W -> f16 only (x transpose now folded into qkv).
// ===========================================================================
__global__ __launch_bounds__(256) void prepw_kernel(
    const float* __restrict__ wq, const float* __restrict__ wk,
    const float* __restrict__ wv, const float* __restrict__ wo)
{
    const int wb = blockIdx.x;                 // 32 blocks
    const int tid = threadIdx.x;
    #pragma unroll
    for (int i = 0; i < 8; ++i) {
        int idx = wb*2048 + i*256 + tid;
        int m = idx >> 14, rr = idx & 16383;
        const float* W = (m==0) ? wq : (m==1) ? wk : (m==2) ? wv : wo;
        g_Wh[idx] = __float2half(W[rr]);
    }
}

// ===========================================================================
// Kernel 1: fused QKV projection, cp.async double-buffered f16 pipeline.
// Reads x fp32 directly: two 64-channel chunks staged fp32 in smem, then
// transposed+converted to the f16 (n, c) tile.  No g_Xh intermediate.
// ===========================================================================
#define XSTR 136
#define WSTR 40
#define XFSTR 68
__global__ __launch_bounds__(256, 2) void qkv_kernel(
    const float* __restrict__ x,
    const float* __restrict__ bq, const float* __restrict__ bk,
    const float* __restrict__ bv)
{
    __shared__ __align__(16) float  Xf[64*XFSTR];    // 17.4 KB (staging, reused)
    __shared__ __align__(16) __half Xs[64*XSTR];     // 17.4 KB
    __shared__ __align__(16) __half Ws[2][128*WSTR]; // 20.5 KB

    const int tile = blockIdx.x;
    const int b  = tile >> 6;
    const int n0 = (tile & 63) << 6;
    const int tid = threadIdx.x;
    const int w = tid >> 5, lane = tid & 31;
    const int wm = w >> 1, wn = w & 1;
    const int g = lane >> 2, t = lane & 3;

    // ---- Preamble: x chunk 0 (channels 0-63) + W chunk 0 ----
    #pragma unroll
    for (int i = 0; i < 4; ++i) {              // 1024 cp16: 64 c-rows x 16
        int idx = tid + i*256;
        int c = idx >> 4, f = idx & 15;
        cp16(&Xf[c*XFSTR + f*4], x + ((size_t)b*Cch + c)*Nn + n0 + f*4);
    }
    #pragma unroll
    for (int i = 0; i < 2; ++i) {              // 512 cp16
        int idx = tid + i*256;
        int o = idx >> 2, sg = idx & 3;
        cp16(&Ws[0][o*WSTR + sg*8], g_Wh + o*Cch + sg*8);
    }
    cp_commit();
    cp_wait0();
    __syncthreads();

    // Convert chunk 0: Xf (c', n) fp32 -> Xs[n][c'] f16 (cols 0-63)
    {
        int c2 = 2*(tid & 31);                 // even c' 0..62
        int nb = (tid >> 5) * 8;
        #pragma unroll
        for (int j = 0; j < 8; ++j) {
            int n = nb + j;
            float lo = Xf[c2*XFSTR + n];
            float hi = Xf[(c2+1)*XFSTR + n];
            *(half2*)&Xs[n*XSTR + c2] = __floats2half2_rn(lo, hi);
        }
    }
    __syncthreads();                           // Xf free for chunk 1

    // ---- x chunk 1 (channels 64-127) ----
    #pragma unroll
    for (int i = 0; i < 4; ++i) {
        int idx = tid + i*256;
        int c = idx >> 4, f = idx & 15;
        cp16(&Xf[c*XFSTR + f*4], x + ((size_t)b*Cch + 64 + c)*Nn + n0 + f*4);
    }
    cp_commit();
    cp_wait0();
    __syncthreads();
    {
        int c2 = 2*(tid & 31);
        int nb = (tid >> 5) * 8;
        #pragma unroll
        for (int j = 0; j < 8; ++j) {
            int n = nb + j;
            float lo = Xf[c2*XFSTR + n];
            float hi = Xf[(c2+1)*XFSTR + n];
            *(half2*)&Xs[n*XSTR + 64 + c2] = __floats2half2_rn(lo, hi);
        }
    }
    // Loop's s=0 cp_wait0 (no pending) + __syncthreads orders converts. 

    float acc[2][4][4];
    for (int s = 0; s < 12; ++s) {
        const int p = s >> 2, kc4 = s & 3, buf = s & 1;
        cp_wait0();
        __syncthreads();
        if (s < 11) {
            const int p2 = (s+1) >> 2, kc2 = (s+1) & 3;
            const __half* src = g_Wh + (size_t)p2*Cch*Cch + kc2*32;
            #pragma unroll
            for (int i = 0; i < 2; ++i) {
                int idx = tid + i*256;
                int o = idx >> 2, sg = idx & 3;
                cp16(&Ws[buf^1][o*WSTR + sg*8], src + (size_t)o*Cch + sg*8);
            }
            cp_commit();
        }

        if (kc4 == 0) {
            const float* bias = (p==0) ? bq : (p==1) ? bk : bv;
            #pragma unroll
            for (int mi = 0; mi < 2; ++mi) {
                float blo = bias[wm*32 + mi*16 + g];
                float bhi = bias[wm*32 + mi*16 + 8 + g];
                #pragma unroll
                for (int n8 = 0; n8 < 4; ++n8) {
                    acc[mi][n8][0] = blo; acc[mi][n8][1] = blo;
                    acc[mi][n8][2] = bhi; acc[mi][n8][3] = bhi;
                }
            }
        }

        #pragma unroll
        for (int k2 = 0; k2 < 2; ++k2) {
            uint32_t af[2][4], bf[2][4];
            #pragma unroll
            for (int mi = 0; mi < 2; ++mi)
                ldmx4(af[mi], &Ws[buf][(wm*32 + mi*16 + (lane&15))*WSTR
                                       + k2*16 + (lane>>4)*8]);
            #pragma unroll
            for (int pr = 0; pr < 2; ++pr)
                ldmx4(bf[pr], &Xs[(wn*32 + pr*16 + (lane>>4)*8 + (lane&7))*XSTR
                                  + kc4*32 + k2*16 + ((lane>>3)&1)*8]);
            #pragma unroll
            for (int mi = 0; mi < 2; ++mi)
                #pragma unroll
                for (int pr = 0; pr < 2; ++pr)
                    #pragma unroll
                    for (int sb = 0; sb < 2; ++sb)
                        mmaf16(acc[mi][pr*2+sb][0], acc[mi][pr*2+sb][1],
                               acc[mi][pr*2+sb][2], acc[mi][pr*2+sb][3],
                               af[mi][0],af[mi][1],af[mi][2],af[mi][3],
                               bf[pr][sb*2], bf[pr][sb*2+1]);
        }

        if (kc4 == 3) {
            const float sc = (p==0) ? QSCALE : 1.0f;
            const size_t bh = (size_t)b*NH + wm;
            #pragma unroll
            for (int mi = 0; mi < 2; ++mi) {
                int dlo = mi*16 + g, dhi = dlo + 8;
                #pragma unroll
                for (int n8 = 0; n8 < 4; ++n8) {
                    int n = n0 + wn*32 + n8*8 + 2*t;
                    if (p < 2) {
                        __half* tgt = (p==0) ? g_Q : g_K;
                        tgt[(bh*Nn + n  )*Dd + dlo] = __float2half(acc[mi][n8][0]*sc);
                        tgt[(bh*Nn + n+1)*Dd + dlo] = __float2half(acc[mi][n8][1]*sc);
                        tgt[(bh*Nn + n  )*Dd + dhi] = __float2half(acc[mi][n8][2]*sc);
                        tgt[(bh*Nn + n+1)*Dd + dhi] = __float2half(acc[mi][n8][3]*sc);
                    } else {
                        *(half2*)&g_Vt[(bh*Dd + dlo)*Nn + n] =
                            __floats2half2_rn(acc[mi][n8][0], acc[mi][n8][1]);
                        *(half2*)&g_Vt[(bh*Dd + dhi)*Nn + n] =
                            __floats2half2_rn(acc[mi][n8][2], acc[mi][n8][3]);
                    }
                }
            }
        }
    }
}

// ===========================================================================
// Kernel 2: flash attention.  S-GEMM with f16 accumulators (mma output IS the
// h2exp2 input AND the PV A-fragment).  Row-sums on the fma pipe via HADD2
// (tile-local f16 partials, flushed to f32 per 128-key tile).
// ===========================================================================
#define KSTR 40
#define VSTR 136
__global__ __launch_bounds__(256, 2) void attn_kernel()
{
    __shared__ __align__(16) __half Qs[256*KSTR];      // 20.0 KB
    __shared__ __align__(16) __half Ks[2][128*KSTR];   // 20.0 KB
    __shared__ __align__(16) __half VTs[2][32*VSTR];   // 17.0 KB

    const int bh  = blockIdx.y;
    const int q0  = blockIdx.x * 256;
    const int tid = threadIdx.x;
    const int w = tid >> 5, lane = tid & 31;
    const int g = lane >> 2, t = lane & 3;
    const int b = bh >> 2, h = bh & 3;

    const __half* Kbase = g_K  + (size_t)bh*Nn*Dd;
    const __half* Vbase = g_Vt + (size_t)bh*Dd*Nn;

    // Preamble: Q tile + K/V tile 0 in one group
    {
        const __half* gq = g_Q + ((size_t)bh*Nn + q0)*Dd;
        #pragma unroll
        for (int i = 0; i < 4; ++i) {
            int idx = tid + i*256;             // 1024 cp16
            int r = idx >> 2, sg = idx & 3;
            cp16(&Qs[r*KSTR + sg*8], gq + (size_t)r*Dd + sg*8);
        }
        #pragma unroll
        for (int i = 0; i < 2; ++i) {          // K: 512 cp16 (128 rows x 64B)
            int idx = tid + i*256;
            int n = idx >> 2, sg = idx & 3;
            cp16(&Ks[0][n*KSTR + sg*8], Kbase + (size_t)n*Dd + sg*8);
        }
        #pragma unroll
        for (int i = 0; i < 2; ++i) {          // V: 512 cp16 (32 rows x 256B)
            int idx = tid + i*256;
            int d = idx >> 4, nb = idx & 15;
            cp16(&VTs[0][d*VSTR + nb*8], Vbase + (size_t)d*Nn + nb*8);
        }
        cp_commit();
    }
    cp_wait0();
    __syncthreads();

    // Q a-frags: 32 rows per warp, 2 m16 x 2 k16
    uint32_t qa[2][2][4];
    #pragma unroll
    for (int mi = 0; mi < 2; ++mi)
        #pragma unroll
        for (int kc = 0; kc < 2; ++kc)
            ldmx4(qa[mi][kc], &Qs[(w*32 + mi*16 + (lane&15))*KSTR
                                  + kc*16 + (lane>>4)*8]);

    float oacc[2][4][4];
    float fsum[2][2];                          // f32 row sums (rows g, g+8)
    #pragma unroll
    for (int mi = 0; mi < 2; ++mi) {
        #pragma unroll
        for (int n8 = 0; n8 < 4; ++n8)
            #pragma unroll
            for (int i = 0; i < 4; ++i) oacc[mi][n8][i] = 0.f;
        fsum[mi][0] = 0.f; fsum[mi][1] = 0.f;
    }

    for (int it = 0; it < Nn/128; ++it) {
        const int p = it & 1;
        if (it > 0) {
            cp_wait0();
            __syncthreads();
        }
        if (it < Nn/128 - 1) {
            const int k0n = (it+1) * 128;
            #pragma unroll
            for (int i = 0; i < 2; ++i) {
                int idx = tid + i*256;
                int n = idx >> 2, sg = idx & 3;
                cp16(&Ks[p^1][n*KSTR + sg*8], Kbase + (size_t)(k0n + n)*Dd + sg*8);
            }
            #pragma unroll
            for (int i = 0; i < 2; ++i) {
                int idx = tid + i*256;
                int d = idx >> 4, nb = idx & 15;
                cp16(&VTs[p^1][d*VSTR + nb*8], Vbase + (size_t)d*Nn + k0n + nb*8);
            }
            cp_commit();
        }

        // Tile-local f16 row-sum partials (magnitude <= ~30, safe in f16)
        __half2 tsum[2][2];
        tsum[0][0] = tsum[0][1] = tsum[1][0] = tsum[1][1] =
            __floats2half2_rn(0.f, 0.f);

        #pragma unroll
        for (int kc = 0; kc < 8; ++kc) {       // 16 keys per chunk
            // --- S (f16 accum) for keys kc*16..kc*16+15, exp2 in place ---
            uint32_t kb0[4], kb1[4];
            ldmx4(kb0, &Ks[p][((kc*2  )*8 + (lane&7))*KSTR + (lane>>3)*8]);
            ldmx4(kb1, &Ks[p][((kc*2+1)*8 + (lane&7))*KSTR + (lane>>3)*8]);
            uint32_t pa[2][4];
            #pragma unroll
            for (int mi = 0; mi < 2; ++mi) {
                uint32_t c0=0,c1=0,d0=0,d1=0;
                mmah16(c0,c1, qa[mi][0][0],qa[mi][0][1],qa[mi][0][2],qa[mi][0][3],
                       kb0[0],kb0[1]);
                mmah16(c0,c1, qa[mi][1][0],qa[mi][1][1],qa[mi][1][2],qa[mi][1][3],
                       kb0[2],kb0[3]);
                mmah16(d0,d1, qa[mi][0][0],qa[mi][0][1],qa[mi][0][2],qa[mi][0][3],
                       kb1[0],kb1[1]);
                mmah16(d0,d1, qa[mi][1][0],qa[mi][1][1],qa[mi][1][2],qa[mi][1][3],
                       kb1[2],kb1[3]);
                // exp2 directly on the f16x2 accumulators -> PV A-fragments
                pa[mi][0] = h2u(h2exp2(u2h(c0)));
                pa[mi][1] = h2u(h2exp2(u2h(c1)));
                pa[mi][2] = h2u(h2exp2(u2h(d0)));
                pa[mi][3] = h2u(h2exp2(u2h(d1)));
                // row-sum partials on the fma pipe
                tsum[mi][0] = __hadd2(tsum[mi][0],
                                      __hadd2(u2h(pa[mi][0]), u2h(pa[mi][2])));
                tsum[mi][1] = __hadd2(tsum[mi][1],
                                      __hadd2(u2h(pa[mi][1]), u2h(pa[mi][3])));
            }
            // --- V frags, then O += P V ---
            uint32_t vb[4][2];
            #pragma unroll
            for (int n8 = 0; n8 < 4; ++n8)
                ldmx2(vb[n8], &VTs[p][(n8*8 + (lane&7))*VSTR
                                      + kc*16 + ((lane>>3)&1)*8]);
            #pragma unroll
            for (int mi = 0; mi < 2; ++mi) {
                #pragma unroll
                for (int n8 = 0; n8 < 4; ++n8)
                    mmaf16(oacc[mi][n8][0],oacc[mi][n8][1],
                           oacc[mi][n8][2],oacc[mi][n8][3],
                           pa[mi][0],pa[mi][1],pa[mi][2],pa[mi][3],
                           vb[n8][0], vb[n8][1]);
            }
        }

        // Flush tile partials to f32
        #pragma unroll
        for (int mi = 0; mi < 2; ++mi) {
            float2 f0 = __half22float2(tsum[mi][0]);
            float2 f1 = __half22float2(tsum[mi][1]);
            fsum[mi][0] += f0.x + f0.y;
            fsum[mi][1] += f1.x + f1.y;
        }
    }

    // Normalize and store to (b, n, c) f16 token-major.
    #pragma unroll
    for (int mi = 0; mi < 2; ++mi) {
        float sg = fsum[mi][0];
        sg += __shfl_xor_sync(0xffffffffu, sg, 1);
        sg += __shfl_xor_sync(0xffffffffu, sg, 2);
        float sh = fsum[mi][1];
        sh += __shfl_xor_sync(0xffffffffu, sh, 1);
        sh += __shfl_xor_sync(0xffffffffu, sh, 2);
        float invg  = 1.f / sg;
        float invg8 = 1.f / sh;
        int nlo = q0 + w*32 + mi*16 + g;
        __half* rowlo = g_attnh + ((size_t)b*Nn + nlo    )*Cch + h*Dd;
        __half* rowhi = g_attnh + ((size_t)b*Nn + nlo + 8)*Cch + h*Dd;
        #pragma unroll
        for (int n8 = 0; n8 < 4; ++n8) {
            int d = n8*8 + 2*t;
            *(half2*)(rowlo + d) = __floats2half2_rn(oacc[mi][n8][0]*invg,
                                                     oacc[mi][n8][1]*invg);
            *(half2*)(rowhi + d) = __floats2half2_rn(oacc[mi][n8][2]*invg8,
                                                     oacc[mi][n8][3]*invg8);
        }
    }
}

// ===========================================================================
// Kernel 3: output projection + residual, cp.async pipelined f16 mma.
// ===========================================================================
__global__ __launch_bounds__(256, 2) void oproj_kernel(
    const float* __restrict__ x,
    const float* __restrict__ bo,
    float* __restrict__ out)
{
    __shared__ __align__(16) __half As[64*XSTR];
    __shared__ __align__(16) __half Ws[2][128*WSTR];

    const int tile = blockIdx.x;
    const int b  = tile >> 6;
    const int n0 = (tile & 63) << 6;
    const int tid = threadIdx.x;
    const int w = tid >> 5, lane = tid & 31;
    const int wm = w >> 1, wn = w & 1;
    const int g = lane >> 2, t = lane & 3;

    const __half* Wo = g_Wh + (size_t)3*Cch*Cch;

    #pragma unroll
    for (int i = 0; i < 4; ++i) {
        int idx = tid + i*256;
        int n = idx >> 4, sg = idx & 15;
        cp16(&As[n*XSTR + sg*8], g_attnh + ((size_t)b*Nn + n0 + n)*Cch + sg*8);
    }
    #pragma unroll
    for (int i = 0; i < 2; ++i) {
        int idx = tid + i*256;
        int o = idx >> 2, sg = idx & 3;
        cp16(&Ws[0][o*WSTR + sg*8], Wo + (size_t)o*Cch + sg*8);
    }
    cp_commit();

    float acc[2][4][4];
    #pragma unroll
    for (int mi = 0; mi < 2; ++mi) {
        float blo = bo[wm*32 + mi*16 + g];
        float bhi = bo[wm*32 + mi*16 + 8 + g];
        #pragma unroll
        for (int n8 = 0; n8 < 4; ++n8) {
            acc[mi][n8][0] = blo; acc[mi][n8][1] = blo;
            acc[mi][n8][2] = bhi; acc[mi][n8][3] = bhi;
        }
    }

    for (int s = 0; s < 4; ++s) {
        const int buf = s & 1;
        cp_wait0();
        __syncthreads();
        if (s < 3) {
            const __half* src = Wo + (s+1)*32;
            #pragma unroll
            for (int i = 0; i < 2; ++i) {
                int idx = tid + i*256;
                int o = idx >> 2, sg = idx & 3;
                cp16(&Ws[buf^1][o*WSTR + sg*8], src + (size_t)o*Cch + sg*8);
            }
            cp_commit();
        }

        #pragma unroll
        for (int k2 = 0; k2 < 2; ++k2) {
            uint32_t af[2][4], bf[2][4];
            #pragma unroll
            for (int mi = 0; mi < 2; ++mi)
                ldmx4(af[mi], &Ws[buf][(wm*32 + mi*16 + (lane&15))*WSTR
                                       + k2*16 + (lane>>4)*8]);
            #pragma unroll
            for (int pr = 0; pr < 2; ++pr)
                ldmx4(bf[pr], &As[(wn*32 + pr*16 + (lane>>4)*8 + (lane&7))*XSTR
                                  + s*32 + k2*16 + ((lane>>3)&1)*8]);
            #pragma unroll
            for (int mi = 0; mi < 2; ++mi)
                #pragma unroll
                for (int pr = 0; pr < 2; ++pr)
                    #pragma unroll
                    for (int sb = 0; sb < 2; ++sb)
                        mmaf16(acc[mi][pr*2+sb][0], acc[mi][pr*2+sb][1],
                               acc[mi][pr*2+sb][2], acc[mi][pr*2+sb][3],
                               af[mi][0],af[mi][1],af[mi][2],af[mi][3],
                               bf[pr][sb*2], bf[pr][sb*2+1]);
        }
    }

    #pragma unroll
    for (int mi = 0; mi < 2; ++mi) {
        int olo = wm*32 + mi*16 + g, ohi = olo + 8;
        #pragma unroll
        for (int n8 = 0; n8 < 4; ++n8) {
            int n = n0 + wn*32 + n8*8 + 2*t;
            size_t ilo = ((size_t)b*Cch + olo)*Nn + n;
            size_t ihi = ((size_t)b*Cch + ohi)*Nn + n;
            float2 xlo = *(const float2*)(x + ilo);
            float2 xhi = *(const float2*)(x + ihi);
            float2 r0; r0.x = xlo.x + acc[mi][n8][0]; r0.y = xlo.y + acc[mi][n8][1];
            float2 r1; r1.x = xhi.x + acc[mi][n8][2]; r1.y = xhi.y + acc[mi][n8][3];
            *(float2*)(out + ilo) = r0;
            *(float2*)(out + ihi) = r1;
        }
    }
}

// ---------------------------------------------------------------------------
extern "C" void kernel_launch(void* const* d_in, const int* in_sizes, int n_in,
                              void* d_out, int out_size)
{
    const float* x  = (const float*)d_in[0];
    const float* wq = (const float*)d_in[1];
    const float* bq = (const float*)d_in[2];
    const float* wk = (const float*)d_in[3];
    const float* bk = (const float*)d_in[4];
    const float* wv = (const float*)d_in[5];
    const float* bv = (const float*)d_in[6];
    const float* wo = (const float*)d_in[7];
    const float* bo = (const float*)d_in[8];
    float* out = (float*)d_out;

    prepw_kernel<<<32, 256>>>(wq, wk, wv, wo);
    qkv_kernel<<<Bsz*(Nn/64), 256>>>(x, bq, bk, bv);
    attn_kernel<<<dim3(Nn/256, Bsz*NH), 256>>>();
    oproj_kernel<<<Bsz*(Nn/64), 256>>>(x, bo, out);
}